// round 12
// baseline (speedup 1.0000x reference)
#include <cuda_runtime.h>
#include <cstdint>

#define NN 20000
#define EE 320000
#define CC 128
#define BB 20
#define RCUT_F 5.0f
#define EPS_F 1e-8f

// ---------------- scratch (device globals; no allocation allowed) ----------------
__device__ float g_x  [NN * 3 * CC];   // per-node context net output [N,3C]
__device__ float g_q1 [NN * CC];       // q + dq (accumulated)
__device__ float g_mu1[NN * 3 * CC];   // mu + dmu (accumulated)
__device__ float g_muV[NN * 3 * CC];
__device__ float g_muW[NN * 3 * CC];

// ---------------- helpers ----------------
__device__ __forceinline__ void red4(float* p, float4 v) {
    asm volatile("red.global.add.v4.f32 [%0], {%1,%2,%3,%4};"
                 :: "l"(p), "f"(v.x), "f"(v.y), "f"(v.z), "f"(v.w) : "memory");
}
__device__ __forceinline__ float siluf(float x) {
    return x * (1.0f / (1.0f + __expf(-x)));
}
// packed fp32x2 FMA (Blackwell FFMA2): d = a*b + d
__device__ __forceinline__ void fma2(uint64_t& d, uint64_t a, uint64_t b) {
    asm("fma.rn.f32x2 %0, %1, %2, %0;" : "+l"(d) : "l"(a), "l"(b));
}
__device__ __forceinline__ uint64_t pk(float lo, float hi) {
    uint64_t r; asm("mov.b64 %0, {%1, %2};" : "=l"(r) : "f"(lo), "f"(hi)); return r;
}
__device__ __forceinline__ uint64_t bcast2(float w) {
    uint64_t r; asm("mov.b64 %0, {%1, %1};" : "=l"(r) : "f"(w)); return r;
}
__device__ __forceinline__ float2 unpk(uint64_t p) {
    float2 r; asm("mov.b64 {%0, %1}, %2;" : "=f"(r.x), "=f"(r.y) : "l"(p)); return r;
}
// cp.async (LDGSTS): zero-register weight staging
__device__ __forceinline__ void cpa16(uint32_t dst, const float* src) {
    asm volatile("cp.async.cg.shared.global [%0], [%1], 16;" :: "r"(dst), "l"(src));
}
#define CP_COMMIT() asm volatile("cp.async.commit_group;" ::: "memory")
#define CP_WAIT0()  asm volatile("cp.async.wait_group 0;" ::: "memory")

// Node-GEMV tiling: 256 threads, 32 nodes/block.
// thread = (d = tid&127 output channel, h = tid>>7 node-half); each half owns 16 nodes.
#define NPB 32
#define NHF 16
#define STR 36   // padded tile row stride in floats (144B; 16B-aligned)

// ============================================================================
// K1: context net  x = silu(q@W1+b1)@W2+b2 ; seed g_q1=q, g_mu1=mu
// ============================================================================
#define K1R1 16            // k-rows/tile, layer1 (W1: [128][128])
#define K1T1 (CC / K1R1)   // 8 tiles
#define K1R2 8             // k-rows/tile, layer2 (W2: [128][384])
#define K1T2 (CC / K1R2)   // 16 tiles

__global__ __launch_bounds__(256, 2) void k_context(
    const float* __restrict__ q, const float* __restrict__ mu,
    const float* __restrict__ W1, const float* __restrict__ b1,
    const float* __restrict__ W2, const float* __restrict__ b2)
{
    __shared__ __align__(16) float sqT[CC * STR];        // [k][n]
    __shared__ __align__(16) float shT[CC * STR];        // [k][n]
    __shared__ __align__(16) float sW[2][3 * CC * K1R2]; // 24 KB
    const int tid  = threadIdx.x;
    const int d    = tid & 127;
    const int h    = tid >> 7;
    const int base = blockIdx.x * NPB;
    const uint32_t swb0 = (uint32_t)__cvta_generic_to_shared(sW[0]);
    const uint32_t swb1 = (uint32_t)__cvta_generic_to_shared(sW[1]);

    #pragma unroll
    for (int n2 = 0; n2 < NHF; n2++) {
        const int n = n2 * 2 + h;
        float v = q[(base + n) * CC + d];
        sqT[d * STR + n] = v;
        g_q1[(base + n) * CC + d] = v;
    }
    {
        const float4* src = reinterpret_cast<const float4*>(&mu[base * 3 * CC]);
        float4* dst = reinterpret_cast<float4*>(&g_mu1[base * 3 * CC]);
        #pragma unroll
        for (int t = tid; t < NPB * 3 * CC / 4; t += 256) dst[t] = src[t];
    }
    __syncthreads();

    // ---- layer 1: h = silu(q @ W1 + b1) ----
    uint64_t acc[8];
    {
        float bb = b1[d];
        uint64_t bi = pk(bb, bb);
        #pragma unroll
        for (int m = 0; m < 8; m++) acc[m] = bi;

        #pragma unroll
        for (int t = tid; t < K1R1 * CC / 4; t += 256)
            cpa16(swb0 + t * 16, W1 + t * 4);
        CP_COMMIT();

        for (int kt = 0; kt < K1T1; kt++) {
            CP_WAIT0();
            __syncthreads();
            if (kt + 1 < K1T1) {
                const float* src = W1 + (kt + 1) * K1R1 * CC;
                uint32_t dstb = ((kt + 1) & 1) ? swb1 : swb0;
                #pragma unroll
                for (int t = tid; t < K1R1 * CC / 4; t += 256)
                    cpa16(dstb + t * 16, src + t * 4);
                CP_COMMIT();
            }
            const float* sWt = sW[kt & 1];
            #pragma unroll
            for (int r = 0; r < K1R1; r++) {
                const int k = kt * K1R1 + r;
                uint64_t ww = bcast2(sWt[r * CC + d]);
                const ulonglong2* row = reinterpret_cast<const ulonglong2*>(&sqT[k * STR + h * NHF]);
                #pragma unroll
                for (int m2 = 0; m2 < 4; m2++) {
                    ulonglong2 v = row[m2];
                    fma2(acc[2*m2],   v.x, ww);
                    fma2(acc[2*m2+1], v.y, ww);
                }
            }
        }
    }
    __syncthreads();
    #pragma unroll
    for (int m = 0; m < 8; m++) {
        float2 p = unpk(acc[m]);
        shT[d * STR + h * NHF + 2*m]     = siluf(p.x);
        shT[d * STR + h * NHF + 2*m + 1] = siluf(p.y);
    }
    __syncthreads();

    // ---- layer 2: x = h @ W2 + b2, 3 groups fused ----
    {
        uint64_t a2[3][8];
        #pragma unroll
        for (int g = 0; g < 3; g++) {
            float bb = b2[g * CC + d];
            uint64_t bi = pk(bb, bb);
            #pragma unroll
            for (int m = 0; m < 8; m++) a2[g][m] = bi;
        }
        #pragma unroll
        for (int t = tid; t < K1R2 * 3 * CC / 4; t += 256)
            cpa16(swb0 + t * 16, W2 + t * 4);
        CP_COMMIT();

        for (int kt = 0; kt < K1T2; kt++) {
            CP_WAIT0();
            __syncthreads();
            if (kt + 1 < K1T2) {
                const float* src = W2 + (kt + 1) * K1R2 * 3 * CC;
                uint32_t dstb = ((kt + 1) & 1) ? swb1 : swb0;
                #pragma unroll
                for (int t = tid; t < K1R2 * 3 * CC / 4; t += 256)
                    cpa16(dstb + t * 16, src + t * 4);
                CP_COMMIT();
            }
            const float* sWt = sW[kt & 1];
            #pragma unroll
            for (int r = 0; r < K1R2; r++) {
                const int k = kt * K1R2 + r;
                uint64_t w0 = bcast2(sWt[r * 3 * CC + 0 * CC + d]);
                uint64_t w1 = bcast2(sWt[r * 3 * CC + 1 * CC + d]);
                uint64_t w2 = bcast2(sWt[r * 3 * CC + 2 * CC + d]);
                const ulonglong2* row = reinterpret_cast<const ulonglong2*>(&shT[k * STR + h * NHF]);
                #pragma unroll
                for (int m2 = 0; m2 < 4; m2++) {
                    ulonglong2 v = row[m2];
                    fma2(a2[0][2*m2], v.x, w0); fma2(a2[0][2*m2+1], v.y, w0);
                    fma2(a2[1][2*m2], v.x, w1); fma2(a2[1][2*m2+1], v.y, w1);
                    fma2(a2[2][2*m2], v.x, w2); fma2(a2[2][2*m2+1], v.y, w2);
                }
            }
        }
        #pragma unroll
        for (int g = 0; g < 3; g++) {
            #pragma unroll
            for (int m = 0; m < 8; m++) {
                float2 p = unpk(a2[g][m]);
                g_x[(base + h * NHF + 2*m)     * 3 * CC + g * CC + d] = p.x;
                g_x[(base + h * NHF + 2*m + 1) * 3 * CC + g * CC + d] = p.y;
            }
        }
    }
}

// ============================================================================
// K2: edge kernel. One warp per 4 edges, Wf staged in smem, FFMA2 filter GEMV,
// gather x[j],mu[j] from L2, red.v4 scatter into g_q1/g_mu1.  (unchanged)
// ============================================================================
#define EPW 4
#define EWARPS 8

__global__ __launch_bounds__(256) void k_edge(
    const int*   __restrict__ eidx,     // [2,E]
    const float* __restrict__ ew,       // [E]
    const float* __restrict__ evs,      // [E,3]
    const float* __restrict__ attrs,    // [E,B]
    const float* __restrict__ Wf,       // [B,3C]
    const float* __restrict__ bf,       // [3C]
    const float* __restrict__ mu)       // [N,3,C]
{
    __shared__ __align__(16) float sWf[BB * 3 * CC];
    __shared__ __align__(16) float sbf[3 * CC];

    for (int t = threadIdx.x; t < BB * 3 * CC / 4; t += 256)
        reinterpret_cast<float4*>(sWf)[t] = reinterpret_cast<const float4*>(Wf)[t];
    for (int t = threadIdx.x; t < 3 * CC / 4; t += 256)
        reinterpret_cast<float4*>(sbf)[t] = reinterpret_cast<const float4*>(bf)[t];
    __syncthreads();

    const int lane  = threadIdx.x & 31;
    const int wid   = threadIdx.x >> 5;
    const int c0    = lane * 4;
    const int nwarp = gridDim.x * EWARPS;

    const float4 bq = *reinterpret_cast<const float4*>(&sbf[c0]);
    const float4 bR = *reinterpret_cast<const float4*>(&sbf[CC + c0]);
    const float4 bm = *reinterpret_cast<const float4*>(&sbf[2 * CC + c0]);

    for (int gidx = blockIdx.x * EWARPS + wid; gidx < EE / EPW; gidx += nwarp) {
        const int e0 = gidx * EPW;
        int ii[EPW], jj[EPW];
        float fc[EPW], av[EPW];
        #pragma unroll
        for (int t = 0; t < EPW; t++) {
            ii[t] = eidx[e0 + t];
            jj[t] = eidx[EE + e0 + t];
            float w = ew[e0 + t];
            fc[t] = (w < RCUT_F)
                ? 0.5f * (__cosf((3.14159265358979f / RCUT_F) * w) + 1.0f) : 0.0f;
            av[t] = (lane < BB) ? attrs[(e0 + t) * BB + lane] : 0.0f;
        }

        uint64_t acc[EPW][6];
        #pragma unroll
        for (int t = 0; t < EPW; t++) {
            acc[t][0] = pk(bq.x, bq.y); acc[t][1] = pk(bq.z, bq.w);
            acc[t][2] = pk(bR.x, bR.y); acc[t][3] = pk(bR.z, bR.w);
            acc[t][4] = pk(bm.x, bm.y); acc[t][5] = pk(bm.z, bm.w);
        }

        #pragma unroll
        for (int b = 0; b < BB; b++) {
            ulonglong2 f0 = *reinterpret_cast<const ulonglong2*>(&sWf[b * 3 * CC + c0]);
            ulonglong2 f1 = *reinterpret_cast<const ulonglong2*>(&sWf[b * 3 * CC + CC + c0]);
            ulonglong2 f2 = *reinterpret_cast<const ulonglong2*>(&sWf[b * 3 * CC + 2 * CC + c0]);
            #pragma unroll
            for (int t = 0; t < EPW; t++) {
                uint64_t aw = bcast2(__shfl_sync(0xFFFFFFFFu, av[t], b));
                fma2(acc[t][0], f0.x, aw); fma2(acc[t][1], f0.y, aw);
                fma2(acc[t][2], f1.x, aw); fma2(acc[t][3], f1.y, aw);
                fma2(acc[t][4], f2.x, aw); fma2(acc[t][5], f2.y, aw);
            }
        }

        #pragma unroll
        for (int t = 0; t < EPW; t++) {
            const int e = e0 + t;
            const float f = fc[t];
            const float ev0 = evs[e * 3 + 0];
            const float ev1 = evs[e * 3 + 1];
            const float ev2 = evs[e * 3 + 2];

            float2 wq0 = unpk(acc[t][0]), wq1 = unpk(acc[t][1]);
            float2 wR0 = unpk(acc[t][2]), wR1 = unpk(acc[t][3]);
            float2 wm0 = unpk(acc[t][4]), wm1 = unpk(acc[t][5]);

            const float4* xb = reinterpret_cast<const float4*>(&g_x[jj[t] * 3 * CC]);
            float4 x0 = xb[lane];
            float4 x1 = xb[32 + lane];
            float4 x2 = xb[64 + lane];

            float4 dq = make_float4(x0.x * wq0.x * f, x0.y * wq0.y * f,
                                    x0.z * wq1.x * f, x0.w * wq1.y * f);
            red4(&g_q1[ii[t] * CC + c0], dq);

            float4 cR = make_float4(x1.x * wR0.x * f, x1.y * wR0.y * f,
                                    x1.z * wR1.x * f, x1.w * wR1.y * f);
            float4 cm = make_float4(x2.x * wm0.x * f, x2.y * wm0.y * f,
                                    x2.z * wm1.x * f, x2.w * wm1.y * f);

            const float4* mub = reinterpret_cast<const float4*>(&mu[jj[t] * 3 * CC]);
            #pragma unroll
            for (int v = 0; v < 3; v++) {
                float evv = (v == 0) ? ev0 : (v == 1) ? ev1 : ev2;
                float4 mj = mub[v * 32 + lane];
                float4 dm = make_float4(fmaf(cm.x, mj.x, cR.x * evv),
                                        fmaf(cm.y, mj.y, cR.y * evv),
                                        fmaf(cm.z, mj.z, cR.z * evv),
                                        fmaf(cm.w, mj.w, cR.w * evv));
                red4(&g_mu1[(ii[t] * 3 + v) * CC + c0], dm);
            }
        }
    }
}

// ============================================================================
// K3a: mu_mix = mu1 @ W_mix -> muV, muW. mu1 treated as [3N,128]; 32 rows/blk.
// ============================================================================
#define K3R 8
#define K3T (CC / K3R)   // 16 tiles

__global__ __launch_bounds__(256, 3) void k_mumix(const float* __restrict__ Wmix)
{
    __shared__ __align__(16) float sT[CC * STR];
    __shared__ __align__(16) float sW[2][K3R * 2 * CC];   // 16 KB
    const int tid  = threadIdx.x;
    const int d    = tid & 127;
    const int h    = tid >> 7;
    const int base = blockIdx.x * NPB;
    const uint32_t swb0 = (uint32_t)__cvta_generic_to_shared(sW[0]);
    const uint32_t swb1 = (uint32_t)__cvta_generic_to_shared(sW[1]);

    #pragma unroll
    for (int n2 = 0; n2 < NHF; n2++) {
        const int r = n2 * 2 + h;
        sT[d * STR + r] = g_mu1[(base + r) * CC + d];
    }
    __syncthreads();

    uint64_t acc[2][8];
    #pragma unroll
    for (int g = 0; g < 2; g++)
        #pragma unroll
        for (int m = 0; m < 8; m++) acc[g][m] = 0ull;

    #pragma unroll
    for (int t = tid; t < K3R * 2 * CC / 4; t += 256)
        cpa16(swb0 + t * 16, Wmix + t * 4);
    CP_COMMIT();

    for (int kt = 0; kt < K3T; kt++) {
        CP_WAIT0();
        __syncthreads();
        if (kt + 1 < K3T) {
            const float* src = Wmix + (kt + 1) * K3R * 2 * CC;
            uint32_t dstb = ((kt + 1) & 1) ? swb1 : swb0;
            #pragma unroll
            for (int t = tid; t < K3R * 2 * CC / 4; t += 256)
                cpa16(dstb + t * 16, src + t * 4);
            CP_COMMIT();
        }
        const float* sWt = sW[kt & 1];
        #pragma unroll
        for (int r = 0; r < K3R; r++) {
            const int k = kt * K3R + r;
            uint64_t w0 = bcast2(sWt[r * 2 * CC + 0 * CC + d]);
            uint64_t w1 = bcast2(sWt[r * 2 * CC + 1 * CC + d]);
            const ulonglong2* row = reinterpret_cast<const ulonglong2*>(&sT[k * STR + h * NHF]);
            #pragma unroll
            for (int m2 = 0; m2 < 4; m2++) {
                ulonglong2 v = row[m2];
                fma2(acc[0][2*m2], v.x, w0); fma2(acc[0][2*m2+1], v.y, w0);
                fma2(acc[1][2*m2], v.x, w1); fma2(acc[1][2*m2+1], v.y, w1);
            }
        }
    }
    #pragma unroll
    for (int g = 0; g < 2; g++) {
        float* dst = (g == 0) ? g_muV : g_muW;
        #pragma unroll
        for (int m = 0; m < 8; m++) {
            float2 p = unpk(acc[g][m]);
            dst[(base + h * NHF + 2*m)     * CC + d] = p.x;
            dst[(base + h * NHF + 2*m + 1) * CC + d] = p.y;
        }
    }
}

// ============================================================================
// K3b: mixing MLP + final outputs. 32 nodes/block, 256 threads.
// ============================================================================
#define K4R1 16                // layer1 tile rows (Wm1: [256][128])
#define K4T1 (2 * CC / K4R1)   // 16 tiles
#define K4R2 8                 // layer2 tile rows (Wm2: [128][384])
#define K4T2 (CC / K4R2)       // 16 tiles

__global__ __launch_bounds__(256, 2) void k_mixout(
    const float* __restrict__ Wm1, const float* __restrict__ bm1,
    const float* __restrict__ Wm2, const float* __restrict__ bm2,
    float* __restrict__ out_q, float* __restrict__ out_mu)
{
    __shared__ __align__(16) float buf[2 * CC * STR];     // 36.9 KB
    __shared__ __align__(16) float sscal[NPB * CC];       // 16 KB
    __shared__ __align__(16) float sW[2][3 * CC * K4R2];  // 24 KB
    const int tid  = threadIdx.x;
    const int d    = tid & 127;
    const int h    = tid >> 7;
    const int base = blockIdx.x * NPB;
    const uint32_t swb0 = (uint32_t)__cvta_generic_to_shared(sW[0]);
    const uint32_t swb1 = (uint32_t)__cvta_generic_to_shared(sW[1]);

    // prologue: ctx tile (q1, |mu_V|) + scal = <mu_V, mu_W> per (node,d)
    #pragma unroll
    for (int n2 = 0; n2 < NHF; n2++) {
        const int n = n2 * 2 + h;
        const int node = base + n;
        float q1v = g_q1[node * CC + d];
        float v0 = g_muV[(node * 3 + 0) * CC + d];
        float v1 = g_muV[(node * 3 + 1) * CC + d];
        float v2 = g_muV[(node * 3 + 2) * CC + d];
        float w0 = g_muW[(node * 3 + 0) * CC + d];
        float w1 = g_muW[(node * 3 + 1) * CC + d];
        float w2 = g_muW[(node * 3 + 2) * CC + d];
        float vn = sqrtf(fmaf(v0, v0, fmaf(v1, v1, fmaf(v2, v2, EPS_F))));
        sscal[n * CC + d] = fmaf(v0, w0, fmaf(v1, w1, v2 * w2));
        buf[d * STR + n] = q1v;
        buf[(CC + d) * STR + n] = vn;
    }
    __syncthreads();

    // ---- layer 1: hidden = silu(ctx @ Wm1 + bm1) ----
    uint64_t acc[8];
    {
        float bb = bm1[d];
        uint64_t bi = pk(bb, bb);
        #pragma unroll
        for (int m = 0; m < 8; m++) acc[m] = bi;

        #pragma unroll
        for (int t = tid; t < K4R1 * CC / 4; t += 256)
            cpa16(swb0 + t * 16, Wm1 + t * 4);
        CP_COMMIT();

        for (int kt = 0; kt < K4T1; kt++) {
            CP_WAIT0();
            __syncthreads();
            if (kt + 1 < K4T1) {
                const float* src = Wm1 + (kt + 1) * K4R1 * CC;
                uint32_t dstb = ((kt + 1) & 1) ? swb1 : swb0;
                #pragma unroll
                for (int t = tid; t < K4R1 * CC / 4; t += 256)
                    cpa16(dstb + t * 16, src + t * 4);
                CP_COMMIT();
            }
            const float* sWt = sW[kt & 1];
            #pragma unroll
            for (int r = 0; r < K4R1; r++) {
                const int k = kt * K4R1 + r;
                uint64_t ww = bcast2(sWt[r * CC + d]);
                const ulonglong2* row = reinterpret_cast<const ulonglong2*>(&buf[k * STR + h * NHF]);
                #pragma unroll
                for (int m2 = 0; m2 < 4; m2++) {
                    ulonglong2 v = row[m2];
                    fma2(acc[2*m2],   v.x, ww);
                    fma2(acc[2*m2+1], v.y, ww);
                }
            }
        }
    }
    __syncthreads();   // ctx reads done; overwrite vn rows (128..255) with hidden
    #pragma unroll
    for (int m = 0; m < 8; m++) {
        float2 p = unpk(acc[m]);
        buf[(CC + d) * STR + h * NHF + 2*m]     = siluf(p.x);
        buf[(CC + d) * STR + h * NHF + 2*m + 1] = siluf(p.y);
    }
    __syncthreads();

    // ---- layer 2: 3 output groups fused, over hidden rows ----
    uint64_t a[3][8];
    #pragma unroll
    for (int g = 0; g < 3; g++) {
        float bb = bm2[g * CC + d];
        uint64_t bi = pk(bb, bb);
        #pragma unroll
        for (int m = 0; m < 8; m++) a[g][m] = bi;
    }
    #pragma unroll
    for (int t = tid; t < K4R2 * 3 * CC / 4; t += 256)
        cpa16(swb0 + t * 16, Wm2 + t * 4);
    CP_COMMIT();

    for (int kt = 0; kt < K4T2; kt++) {
        CP_WAIT0();
        __syncthreads();
        if (kt + 1 < K4T2) {
            const float* src = Wm2 + (kt + 1) * K4R2 * 3 * CC;
            uint32_t dstb = ((kt + 1) & 1) ? swb1 : swb0;
            #pragma unroll
            for (int t = tid; t < K4R2 * 3 * CC / 4; t += 256)
                cpa16(dstb + t * 16, src + t * 4);
            CP_COMMIT();
        }
        const float* sWt = sW[kt & 1];
        #pragma unroll
        for (int r = 0; r < K4R2; r++) {
            const int k = kt * K4R2 + r;
            uint64_t w0 = bcast2(sWt[r * 3 * CC + 0 * CC + d]);
            uint64_t w1 = bcast2(sWt[r * 3 * CC + 1 * CC + d]);
            uint64_t w2 = bcast2(sWt[r * 3 * CC + 2 * CC + d]);
            const ulonglong2* row = reinterpret_cast<const ulonglong2*>(&buf[(CC + k) * STR + h * NHF]);
            #pragma unroll
            for (int m2 = 0; m2 < 4; m2++) {
                ulonglong2 v = row[m2];
                fma2(a[0][2*m2], v.x, w0); fma2(a[0][2*m2+1], v.y, w0);
                fma2(a[1][2*m2], v.x, w1); fma2(a[1][2*m2+1], v.y, w1);
                fma2(a[2][2*m2], v.x, w2); fma2(a[2][2*m2+1], v.y, w2);
            }
        }
    }

    // epilogue
    #pragma unroll
    for (int m = 0; m < 8; m++) {
        float2 p0 = unpk(a[0][m]);   // dq_intra
        float2 p1 = unpk(a[1][m]);   // dmu_intra
        float2 p2 = unpk(a[2][m]);   // dqmu_intra
        #pragma unroll
        for (int t = 0; t < 2; t++) {
            const int n = h * NHF + 2*m + t;
            const int node = base + n;
            float y0 = t ? p0.y : p0.x;
            float y1 = t ? p1.y : p1.x;
            float y2 = t ? p2.y : p2.x;
            float q1v  = buf[d * STR + n];          // preserved ctx row
            float scal = sscal[n * CC + d];
            out_q[node * CC + d] = q1v + y0 + y2 * scal;
            #pragma unroll
            for (int v = 0; v < 3; v++) {
                float mw = g_muW[(node * 3 + v) * CC + d];
                float m1 = g_mu1[(node * 3 + v) * CC + d];
                out_mu[(node * 3 + v) * CC + d] = fmaf(y1, mw, m1);
            }
        }
    }
}

// ============================================================================
extern "C" void kernel_launch(void* const* d_in, const int* in_sizes, int n_in,
                              void* d_out, int out_size)
{
    const float* q     = (const float*)d_in[0];
    const float* mu    = (const float*)d_in[1];
    const int*   eidx  = (const int*)  d_in[2];
    const float* ew    = (const float*)d_in[3];
    const float* evs   = (const float*)d_in[4];
    const float* attrs = (const float*)d_in[5];
    const float* Wf    = (const float*)d_in[6];
    const float* bf    = (const float*)d_in[7];
    const float* W1    = (const float*)d_in[8];
    const float* b1    = (const float*)d_in[9];
    const float* W2    = (const float*)d_in[10];
    const float* b2    = (const float*)d_in[11];
    const float* Wmix  = (const float*)d_in[12];
    const float* Wm1   = (const float*)d_in[13];
    const float* bm1   = (const float*)d_in[14];
    const float* Wm2   = (const float*)d_in[15];
    const float* bm2   = (const float*)d_in[16];

    float* out_q  = (float*)d_out;
    float* out_mu = out_q + (size_t)NN * CC;

    k_context<<<NN / NPB, 256>>>(q, mu, W1, b1, W2, b2);
    k_edge<<<1184, 256>>>(eidx, ew, evs, attrs, Wf, bf, mu);
    k_mumix<<<(3 * NN) / NPB, 256>>>(Wmix);
    k_mixout<<<NN / NPB, 256>>>(Wm1, bm1, Wm2, bm2, out_q, out_mu);
}